// round 15
// baseline (speedup 1.0000x reference)
#include <cuda_runtime.h>
#include <cuda_bf16.h>
#include <math.h>
#include <stdint.h>

#define DEVI static __device__ __forceinline__

constexpr int Bc = 128, Tc = 512, Tqc = 32, Sc = 64, Gc = 300, Hd = 256;
constexpr int GWc = 512, Vc = 159, H3 = 768, Zc = 1794;

constexpr size_t O_GI_I   = 0;
constexpr size_t O_HIST_I = O_GI_I   + (size_t)Bc * Tc * H3;
constexpr size_t O_GI_Q   = O_HIST_I + (size_t)Tc * Bc * Hd;
constexpr size_t O_HIST_Q = O_GI_Q   + (size_t)Bc * Tqc * H3;
constexpr size_t O_FD     = O_HIST_Q + (size_t)Tqc * Bc * Hd;
constexpr size_t O_P      = O_FD     + (size_t)Bc * Sc * 4 * Hd;
constexpr size_t O_FACTS  = O_P      + (size_t)Bc * Sc * GWc;
constexpr size_t O_HA     = O_FACTS  + (size_t)Bc * Sc * Hd;
constexpr size_t O_QV     = O_HA  + (size_t)Bc * Hd;
constexpr size_t O_MT     = O_QV  + (size_t)Bc * Hd;
constexpr size_t O_UQ     = O_MT  + (size_t)Bc * Hd;
constexpr size_t O_HTC    = O_UQ  + (size_t)Bc * Hd;
constexpr size_t O_QM     = O_HTC + (size_t)Bc * Hd;
constexpr size_t O_CST    = O_QM  + (size_t)Bc * 2 * Hd;
constexpr size_t O_SM     = O_CST + (size_t)Bc * GWc;
constexpr size_t O_SQ     = O_SM  + (size_t)Bc * Sc;
constexpr size_t O_GIB    = O_SQ  + (size_t)Bc * Sc;
constexpr size_t O_GHB    = O_GIB + (size_t)Bc * H3;
constexpr size_t O_XT     = O_GHB + (size_t)Bc * H3;
constexpr size_t O_W7     = O_XT  + (size_t)Bc * (Vc + Hd);
constexpr size_t O_W8     = O_W7  + (size_t)GWc;
constexpr size_t O_F0     = O_W8  + (size_t)GWc;
constexpr size_t O_P0     = O_F0  + (size_t)Bc * Sc * 3 * Hd;
constexpr size_t O_W0     = O_P0  + (size_t)Bc * Sc * GWc;
constexpr size_t O_WD     = O_W0  + (size_t)GWc * 3 * Hd;
constexpr size_t O_AHI    = O_WD  + (size_t)GWc * 2 * Hd;
constexpr size_t O_ALO    = O_AHI + (size_t)Bc * Tc * Gc / 2;
constexpr size_t O_WHI    = O_ALO + (size_t)Bc * Tc * Gc / 2;
constexpr size_t O_WLO    = O_WHI + (size_t)H3 * Gc / 2;
constexpr size_t G_TOTAL  = O_WLO + (size_t)H3 * Gc / 2;

__device__ float g_buf[G_TOTAL];

DEVI float sigf(float x) { return 1.f / (1.f + __expf(-x)); }
DEVI float tanhfast(float x) {
    float ax = fabsf(x);
    float e = __expf(-2.f * ax);
    return copysignf((1.f - e) / (1.f + e), x);
}
DEVI void ffma2(unsigned long long& acc, unsigned long long a, unsigned long long b) {
    asm("fma.rn.f32x2 %0, %1, %2, %0;" : "+l"(acc) : "l"(a), "l"(b));
}
DEVI float hsum2(unsigned long long a) {
    float lo, hi;
    asm("mov.b64 {%0, %1}, %2;" : "=f"(lo), "=f"(hi) : "l"(a));
    return lo + hi;
}
DEVI uint32_t s2u(const void* p) {
    uint32_t a;
    asm("{ .reg .u64 t; cvta.to.shared.u64 t, %1; cvt.u32.u64 %0, t; }" : "=r"(a) : "l"(p));
    return a;
}
DEVI void stclu(uint32_t laddr, uint32_t rk, float v) {
    uint32_t ra;
    asm("mapa.shared::cluster.u32 %0, %1, %2;" : "=r"(ra) : "r"(laddr), "r"(rk));
    asm volatile("st.shared::cluster.f32 [%0], %1;" :: "r"(ra), "f"(v) : "memory");
}
DEVI void mbar_arrive_rk(uint32_t laddr, uint32_t rk) {
    uint32_t ra;
    asm("mapa.shared::cluster.u32 %0, %1, %2;" : "=r"(ra) : "r"(laddr), "r"(rk));
    asm volatile("mbarrier.arrive.release.cluster.shared::cluster.b64 _, [%0];"
                 :: "r"(ra) : "memory");
}
DEVI void mbar_wait(uint32_t addr, uint32_t par) {
    uint32_t done;
    asm volatile("{\n\t.reg .pred p;\n\t"
        "mbarrier.try_wait.parity.acquire.cluster.shared::cta.b64 p, [%1], %2;\n\t"
        "selp.b32 %0, 1, 0, p;\n\t}"
        : "=r"(done) : "r"(addr), "r"(par) : "memory");
    if (!done) {
        asm volatile("{\n\t.reg .pred P1;\n\t"
            "WL%=:\n\t"
            "mbarrier.try_wait.parity.acquire.cluster.shared::cta.b64 P1, [%0], %1, 0x989680;\n\t"
            "@P1 bra.uni DN%=;\n\t"
            "bra.uni WL%=;\n\t"
            "DN%=:\n\t}"
            :: "r"(addr), "r"(par) : "memory");
    }
}

#define LDM4(r, addr) \
    asm volatile("ldmatrix.sync.aligned.m8n8.x4.shared.b16 {%0,%1,%2,%3},[%4];" \
        : "=r"((r)[0]), "=r"((r)[1]), "=r"((r)[2]), "=r"((r)[3]) : "r"(addr))
#define MMA_BF16(d, a, b) \
    asm volatile("mma.sync.aligned.m16n8k16.row.col.f32.bf16.bf16.f32 " \
        "{%0,%1,%2,%3},{%4,%5,%6,%7},{%8,%9},{%0,%1,%2,%3};" \
        : "+f"((d)[0]), "+f"((d)[1]), "+f"((d)[2]), "+f"((d)[3]) \
        : "r"((a)[0]), "r"((a)[1]), "r"((a)[2]), "r"((a)[3]), "r"((b)[0]), "r"((b)[1]))

#define LOAD8(dst, Row, kb, Kv) do { \
    if ((kb) + 8 <= (Kv)) { \
        float4 t0_ = *(const float4*)((Row) + (kb)); \
        float4 t1_ = *(const float4*)((Row) + (kb) + 4); \
        (dst)[0]=t0_.x;(dst)[1]=t0_.y;(dst)[2]=t0_.z;(dst)[3]=t0_.w; \
        (dst)[4]=t1_.x;(dst)[5]=t1_.y;(dst)[6]=t1_.z;(dst)[7]=t1_.w; \
    } else { \
        _Pragma("unroll") for (int j_ = 0; j_ < 8; j_++) { \
            int k_ = (kb) + j_; (dst)[j_] = (k_ < (Kv)) ? (Row)[k_] : 0.f; } \
    } \
} while (0)

#define LD8B(a0, a1, Row, kb, Kv) do { \
    if ((kb) + 8 <= (Kv)) { \
        a0 = *(const uint2*)((Row) + (kb)); \
        a1 = *(const uint2*)((Row) + (kb) + 4); \
    } else { \
        unsigned short t_[8]; \
        _Pragma("unroll") for (int j_ = 0; j_ < 8; j_++) { \
            int k_ = (kb) + j_; t_[j_] = (k_ < (Kv)) ? (Row)[k_] : (unsigned short)0; } \
        a0.x = (uint32_t)t_[0] | ((uint32_t)t_[1] << 16); \
        a0.y = (uint32_t)t_[2] | ((uint32_t)t_[3] << 16); \
        a1.x = (uint32_t)t_[4] | ((uint32_t)t_[5] << 16); \
        a1.y = (uint32_t)t_[6] | ((uint32_t)t_[7] << 16); \
    } \
} while (0)

DEVI unsigned short bfh(float v) { return __bfloat16_as_ushort(__float2bfloat16(v)); }
DEVI float bff(unsigned short u) { return __bfloat162float(__ushort_as_bfloat16(u)); }

// ---- fp32 -> split-bf16 planes (bit-identical to in-kernel conversion) ----
__global__ void split2(unsigned short* __restrict__ hi, unsigned short* __restrict__ lo,
                       const float* __restrict__ src, int n4) {
    int i = blockIdx.x * 256 + threadIdx.x;
    if (i >= n4) return;
    float4 v = ((const float4*)src)[i];
    unsigned short h0 = bfh(v.x), h1 = bfh(v.y), h2 = bfh(v.z), h3 = bfh(v.w);
    uint2 hp, lp;
    hp.x = (uint32_t)h0 | ((uint32_t)h1 << 16);
    hp.y = (uint32_t)h2 | ((uint32_t)h3 << 16);
    lp.x = (uint32_t)bfh(v.x - bff(h0)) | ((uint32_t)bfh(v.y - bff(h1)) << 16);
    lp.y = (uint32_t)bfh(v.z - bff(h2)) | ((uint32_t)bfh(v.w - bff(h3)) << 16);
    ((uint2*)hi)[i] = hp;
    ((uint2*)lo)[i] = lp;
}

// ---- cluster GRU (R11 math) with mbarrier step-sync ------------------------
constexpr int WPF = 260;
constexpr int SMW = 192 * WPF;
constexpr int SMH = 2 * 4 * WPF;
constexpr int SMG = 2 * 768;
constexpr int SMEM_GRUC = (SMW + SMH + SMG) * 4 + 16;

__global__ void __launch_bounds__(256, 1) __cluster_dims__(4, 1, 1)
gru_cluster(const float* __restrict__ GI, float* __restrict__ hist,
            const float* __restrict__ Whh, const float* __restrict__ bhh, int T)
{
    extern __shared__ float smf[];
    float* Wsm  = smf;
    float* hbuf = Wsm + SMW;
    float* gsm  = hbuf + SMH;
    const uint32_t bar_u = s2u(gsm + SMG);
    const int tid = threadIdx.x;
    uint32_t rank; asm("mov.u32 %0, %%cluster_ctarank;" : "=r"(rank));
    const int b0 = (blockIdx.x >> 2) * 4;
    const int c0 = (int)rank * 64;

    for (int i = tid; i < 192 * 64; i += 256) {
        int r = i >> 6, f4 = i & 63;
        int g = r >> 6, cl = r & 63;
        int sw = f4 ^ ((f4 >> 3) & 7);
        ((float4*)(Wsm + r * WPF))[sw] =
            ((const float4*)(Whh + (size_t)(g * 256 + c0 + cl) * 256))[f4];
    }
    for (int i = tid; i < SMH; i += 256) hbuf[i] = 0.f;
    if (tid == 0) {
        asm volatile("mbarrier.init.shared.b64 [%0], %1;" :: "r"(bar_u), "r"(4) : "memory");
        asm volatile("mbarrier.init.shared.b64 [%0], %1;" :: "r"(bar_u + 8), "r"(4) : "memory");
    }

    size_t gioff[3]; int gis[3];
#pragma unroll
    for (int i = 0; i < 3; i++) {
        int j = tid + i * 256;
        int b = j / 192, col = j % 192;
        gioff[i] = ((size_t)(b0 + b) * T) * H3 + (size_t)((col >> 6) * 256 + c0 + (col & 63));
        gis[i] = j;
    }
    float gp[3];
#pragma unroll
    for (int i = 0; i < 3; i++) gp[i] = __ldcg(GI + gioff[i]);
#pragma unroll
    for (int i = 0; i < 3; i++) gsm[gis[i]] = gp[i];
    __syncthreads();
    // peers' h zero-init + mbarrier init must be visible before step 0
    asm volatile("barrier.cluster.arrive.aligned;" ::: "memory");
    asm volatile("barrier.cluster.wait.aligned;" ::: "memory");

    const int ks = tid & 7, rt = tid >> 3;
    const int cl0 = rt, cl1 = rt + 32;
    ulonglong2 wc0[8], wc1[8];
#pragma unroll
    for (int j = 0; j < 8; j++) {
        int sw4 = ((ks * 8 + j) ^ ks) * 4;
        wc0[j] = *(const ulonglong2*)(Wsm + cl0 * WPF + sw4);
        wc1[j] = *(const ulonglong2*)(Wsm + cl1 * WPF + sw4);
    }
    const int w2i = ks >> 2, b1b = (ks >> 1) & 1, b0b = ks & 1;
    const int b_e = 2 * b1b + b0b;
    const int cl_e = w2i ? cl1 : cl0;
    const int cg_e = c0 + cl_e;
    const int f4c_e = cg_e >> 2;
    const int swc_e = (f4c_e ^ ((f4c_e >> 3) & 7)) * 4 + (cg_e & 3);
    const float bhr = bhh[cg_e], bhz = bhh[256 + cg_e], bhn = bhh[512 + cg_e];
    const int go_r = b_e * 192 + cl_e;
    const uint32_t hb_u = s2u(hbuf);
    int cur = 0;

    for (int t = 0; t < T; t++) {
        const float* hc = hbuf + cur * (4 * WPF);
        if (t + 1 < T) {
#pragma unroll
            for (int i = 0; i < 3; i++)
                gp[i] = __ldcg(GI + gioff[i] + (size_t)(t + 1) * H3);
        }
        unsigned long long acc[24];
#pragma unroll
        for (int i = 0; i < 24; i++) acc[i] = 0ull;
#pragma unroll
        for (int j = 0; j < 8; j++) {
            int sw4 = ((ks * 8 + j) ^ ks) * 4;
            ulonglong2 hv[4];
#pragma unroll
            for (int b = 0; b < 4; b++) hv[b] = *(const ulonglong2*)(hc + b * WPF + sw4);
            ulonglong2 w2 = *(const ulonglong2*)(Wsm + (64 + cl0) * WPF + sw4);
            ulonglong2 w3 = *(const ulonglong2*)(Wsm + (64 + cl1) * WPF + sw4);
            ulonglong2 w4 = *(const ulonglong2*)(Wsm + (128 + cl0) * WPF + sw4);
            ulonglong2 w5 = *(const ulonglong2*)(Wsm + (128 + cl1) * WPF + sw4);
#pragma unroll
            for (int b = 0; b < 4; b++) {
                ffma2(acc[0 * 4 + b], hv[b].x, wc0[j].x); ffma2(acc[0 * 4 + b], hv[b].y, wc0[j].y);
                ffma2(acc[1 * 4 + b], hv[b].x, wc1[j].x); ffma2(acc[1 * 4 + b], hv[b].y, wc1[j].y);
                ffma2(acc[2 * 4 + b], hv[b].x, w2.x);     ffma2(acc[2 * 4 + b], hv[b].y, w2.y);
                ffma2(acc[3 * 4 + b], hv[b].x, w3.x);     ffma2(acc[3 * 4 + b], hv[b].y, w3.y);
                ffma2(acc[4 * 4 + b], hv[b].x, w4.x);     ffma2(acc[4 * 4 + b], hv[b].y, w4.y);
                ffma2(acc[5 * 4 + b], hv[b].x, w5.x);     ffma2(acc[5 * 4 + b], hv[b].y, w5.y);
            }
        }
        float s[24];
#pragma unroll
        for (int i = 0; i < 24; i++) s[i] = hsum2(acc[i]);

        float t12[12];
#pragma unroll
        for (int g = 0; g < 3; g++)
#pragma unroll
            for (int b = 0; b < 4; b++) {
                float mine  = w2i ? s[(2 * g + 1) * 4 + b] : s[(2 * g) * 4 + b];
                float other = w2i ? s[(2 * g) * 4 + b]     : s[(2 * g + 1) * 4 + b];
                t12[g * 4 + b] = mine + __shfl_xor_sync(0xffffffffu, other, 4);
            }
        float u6[6];
#pragma unroll
        for (int g = 0; g < 3; g++)
#pragma unroll
            for (int bl = 0; bl < 2; bl++) {
                float mine  = b1b ? t12[g * 4 + 2 + bl] : t12[g * 4 + bl];
                float other = b1b ? t12[g * 4 + bl]     : t12[g * 4 + 2 + bl];
                u6[g * 2 + bl] = mine + __shfl_xor_sync(0xffffffffu, other, 2);
            }
        float v3[3];
#pragma unroll
        for (int g = 0; g < 3; g++) {
            float mine  = b0b ? u6[g * 2 + 1] : u6[g * 2];
            float other = b0b ? u6[g * 2]     : u6[g * 2 + 1];
            v3[g] = mine + __shfl_xor_sync(0xffffffffu, other, 1);
        }

        {
            const float* gb = gsm + (t & 1) * 768;
            float r = sigf(gb[go_r] + v3[0] + bhr);
            float z = sigf(gb[go_r + 64] + v3[1] + bhz);
            float n = tanhfast(gb[go_r + 128] + r * (v3[2] + bhn));
            float ho = hc[b_e * WPF + swc_e];
            float hv = (1.f - z) * n + z * ho;
            hist[((size_t)t * Bc + b0 + b_e) * Hd + cg_e] = hv;
            uint32_t la = hb_u + (uint32_t)((((cur ^ 1) * 4 + b_e) * WPF + swc_e) * 4);
#pragma unroll
            for (uint32_t rk = 0; rk < 4; rk++) stclu(la, rk, hv);
        }
        if (t + 1 < T) {
            float* gd = gsm + ((t + 1) & 1) * 768;
#pragma unroll
            for (int i = 0; i < 3; i++) gd[gis[i]] = gp[i];
        }
        __syncthreads();
        const uint32_t lb = bar_u + (uint32_t)((t & 1) << 3);
        if (tid == 0) {
#pragma unroll
            for (uint32_t rk = 0; rk < 4; rk++) mbar_arrive_rk(lb, rk);
        }
        mbar_wait(lb, (uint32_t)((t >> 1) & 1));
        cur ^= 1;
    }
}

// ---- gemm_mma_pre: split-bf16 GEMM with pre-split A/W planes ---------------
constexpr int SMEM_MMA = 2 * 4 * 128 * 24 * 2;

__global__ void __launch_bounds__(256) gemm_mma_pre(
    float* __restrict__ C,
    const unsigned short* __restrict__ AhG, const unsigned short* __restrict__ AlG,
    const unsigned short* __restrict__ WhG, const unsigned short* __restrict__ WlG,
    const float* __restrict__ bias,
    int M, int N, int K, int lda, int ldw, int ldc)
{
    extern __shared__ unsigned short smu[];
    const int tid = threadIdx.x;
    const int warp = tid >> 5, lane = tid & 31;
    const int m0 = blockIdx.y << 7, n0 = blockIdx.x << 7;
    const int mw = (warp >> 2) * 64, nw = (warp & 3) * 32;
    const int lrow = tid >> 1, lks = (tid & 1) * 8;
    const unsigned short* ArH = AhG + (size_t)(m0 + lrow) * lda;
    const unsigned short* ArL = AlG + (size_t)(m0 + lrow) * lda;
    const unsigned short* WrH = WhG + (size_t)(n0 + lrow) * ldw;
    const unsigned short* WrL = WlG + (size_t)(n0 + lrow) * ldw;
    const uint32_t base_u = s2u(smu);

    float d[16][4];
#pragma unroll
    for (int i = 0; i < 16; i++)
#pragma unroll
        for (int j = 0; j < 4; j++) d[i][j] = 0.f;

    const int nch = (K + 15) >> 4;
    uint2 p0, p1, p2, p3, p4, p5, p6, p7;
    LD8B(p0, p1, ArH, lks, K);
    LD8B(p2, p3, ArL, lks, K);
    LD8B(p4, p5, WrH, lks, K);
    LD8B(p6, p7, WrL, lks, K);
    {
        const int off = lrow * 24 + lks;
        *(uint2*)(smu + off) = p0;          *(uint2*)(smu + off + 4) = p1;
        *(uint2*)(smu + 3072 + off) = p2;   *(uint2*)(smu + 3072 + off + 4) = p3;
        *(uint2*)(smu + 6144 + off) = p4;   *(uint2*)(smu + 6144 + off + 4) = p5;
        *(uint2*)(smu + 9216 + off) = p6;   *(uint2*)(smu + 9216 + off + 4) = p7;
    }
    __syncthreads();

    const int lr16 = lane & 15, kh = (lane >> 4) * 8;
    for (int c = 0; c < nch; c++) {
        if (c + 1 < nch) {
            const int kb = (c + 1) * 16 + lks;
            LD8B(p0, p1, ArH, kb, K);
            LD8B(p2, p3, ArL, kb, K);
            LD8B(p4, p5, WrH, kb, K);
            LD8B(p6, p7, WrL, kb, K);
        }
        {
            const uint32_t bu = base_u + (uint32_t)((c & 1) * 24576);
            uint32_t Afh[4][4], Afl[4][4], Bfh[4][2], Bfl[4][2];
#pragma unroll
            for (int i = 0; i < 4; i++) {
                uint32_t ad = bu + (uint32_t)(((mw + 16 * i + lr16) * 24 + kh) * 2);
                LDM4(Afh[i], ad);
                LDM4(Afl[i], ad + 6144);
            }
#pragma unroll
            for (int jj = 0; jj < 2; jj++) {
                uint32_t ad = bu + 12288 + (uint32_t)(((nw + 16 * jj + lr16) * 24 + kh) * 2);
                uint32_t r[4];
                LDM4(r, ad);
                Bfh[2 * jj][0] = r[0]; Bfh[2 * jj][1] = r[2];
                Bfh[2 * jj + 1][0] = r[1]; Bfh[2 * jj + 1][1] = r[3];
                LDM4(r, ad + 6144);
                Bfl[2 * jj][0] = r[0]; Bfl[2 * jj][1] = r[2];
                Bfl[2 * jj + 1][0] = r[1]; Bfl[2 * jj + 1][1] = r[3];
            }
#pragma unroll
            for (int i = 0; i < 4; i++)
#pragma unroll
                for (int j = 0; j < 4; j++) MMA_BF16(d[i * 4 + j], Afh[i], Bfh[j]);
#pragma unroll
            for (int i = 0; i < 4; i++)
#pragma unroll
                for (int j = 0; j < 4; j++) MMA_BF16(d[i * 4 + j], Afl[i], Bfh[j]);
#pragma unroll
            for (int i = 0; i < 4; i++)
#pragma unroll
                for (int j = 0; j < 4; j++) MMA_BF16(d[i * 4 + j], Afh[i], Bfl[j]);
        }
        __syncthreads();
        if (c + 1 < nch) {
            unsigned short* Ah = smu + ((c + 1) & 1) * 12288;
            const int off = lrow * 24 + lks;
            *(uint2*)(Ah + off) = p0;          *(uint2*)(Ah + off + 4) = p1;
            *(uint2*)(Ah + 3072 + off) = p2;   *(uint2*)(Ah + 3072 + off + 4) = p3;
            *(uint2*)(Ah + 6144 + off) = p4;   *(uint2*)(Ah + 6144 + off + 4) = p5;
            *(uint2*)(Ah + 9216 + off) = p6;   *(uint2*)(Ah + 9216 + off + 4) = p7;
            __syncthreads();
        }
    }

    const int er = lane >> 2, ec = (lane & 3) * 2;
#pragma unroll
    for (int i = 0; i < 4; i++)
#pragma unroll
        for (int j = 0; j < 4; j++) {
            const float* dd = d[i * 4 + j];
            int gm = m0 + mw + 16 * i + er;
            int gn = n0 + nw + 8 * j + ec;
            float v0 = dd[0], v1 = dd[1], v2 = dd[2], v3 = dd[3];
            if (bias) { float bb0 = bias[gn], bb1 = bias[gn + 1]; v0 += bb0; v1 += bb1; v2 += bb0; v3 += bb1; }
            size_t o1 = (size_t)gm * ldc + gn, o2 = (size_t)(gm + 8) * ldc + gn;
            *(float2*)(C + o1) = make_float2(v0, v1);
            *(float2*)(C + o2) = make_float2(v2, v3);
        }
}

// ---- gemm_mma: in-kernel-split bf16 GEMM (used by attention path) ----------
__global__ void __launch_bounds__(256) gemm_mma(
    float* __restrict__ C, const float* __restrict__ A, const float* __restrict__ W,
    const float* __restrict__ bias, const float* __restrict__ init,
    int M, int N, int K, int lda, int ldw, int ldc)
{
    extern __shared__ unsigned short smu[];
    const int tid = threadIdx.x;
    const int warp = tid >> 5, lane = tid & 31;
    const int m0 = blockIdx.y << 7, n0 = blockIdx.x << 7;
    const int mw = (warp >> 2) * 64, nw = (warp & 3) * 32;
    const int lrow = tid >> 1, lks = (tid & 1) * 8;
    const float* Arow = A + (size_t)(m0 + lrow) * lda;
    const float* Wrow = W + (size_t)(n0 + lrow) * ldw;
    const uint32_t base_u = s2u(smu);

    float d[16][4];
#pragma unroll
    for (int i = 0; i < 16; i++)
#pragma unroll
        for (int j = 0; j < 4; j++) d[i][j] = 0.f;

    const int nch = (K + 15) >> 4;
    float pa[8], pw[8];

    LOAD8(pa, Arow, lks, K);
    LOAD8(pw, Wrow, lks, K);
    {
        unsigned short* Ah = smu;
        const int off = lrow * 24 + lks;
#pragma unroll
        for (int j2 = 0; j2 < 4; j2++) {
            float v0 = pa[2 * j2], v1 = pa[2 * j2 + 1];
            unsigned short h0 = bfh(v0), h1 = bfh(v1);
            uint32_t hp = (uint32_t)h0 | ((uint32_t)h1 << 16);
            uint32_t lp = (uint32_t)bfh(v0 - bff(h0)) | ((uint32_t)bfh(v1 - bff(h1)) << 16);
            *(uint32_t*)(Ah + off + 2 * j2) = hp;
            *(uint32_t*)(Ah + 3072 + off + 2 * j2) = lp;
            v0 = pw[2 * j2]; v1 = pw[2 * j2 + 1];
            h0 = bfh(v0); h1 = bfh(v1);
            hp = (uint32_t)h0 | ((uint32_t)h1 << 16);
            lp = (uint32_t)bfh(v0 - bff(h0)) | ((uint32_t)bfh(v1 - bff(h1)) << 16);
            *(uint32_t*)(Ah + 6144 + off + 2 * j2) = hp;
            *(uint32_t*)(Ah + 9216 + off + 2 * j2) = lp;
        }
    }
    __syncthreads();

    const int lr16 = lane & 15, kh = (lane >> 4) * 8;
    for (int c = 0; c < nch; c++) {
        if (c + 1 < nch) {
            const int kb = (c + 1) * 16 + lks;
            LOAD8(pa, Arow, kb, K);
            LOAD8(pw, Wrow, kb, K);
        }
        {
            const uint32_t bu = base_u + (uint32_t)((c & 1) * 24576);
            uint32_t Afh[4][4], Afl[4][4], Bfh[4][2], Bfl[4][2];
#pragma unroll
            for (int i = 0; i < 4; i++) {
                uint32_t ad = bu + (uint32_t)(((mw + 16 * i + lr16) * 24 + kh) * 2);
                LDM4(Afh[i], ad);
                LDM4(Afl[i], ad + 6144);
            }
#pragma unroll
            for (int jj = 0; jj < 2; jj++) {
                uint32_t ad = bu + 12288 + (uint32_t)(((nw + 16 * jj + lr16) * 24 + kh) * 2);
                uint32_t r[4];
                LDM4(r, ad);
                Bfh[2 * jj][0] = r[0]; Bfh[2 * jj][1] = r[2];
                Bfh[2 * jj + 1][0] = r[1]; Bfh[2 * jj + 1][1] = r[3];
                LDM4(r, ad + 6144);
                Bfl[2 * jj][0] = r[0]; Bfl[2 * jj][1] = r[2];
                Bfl[2 * jj + 1][0] = r[1]; Bfl[2 * jj + 1][1] = r[3];
            }
#pragma unroll
            for (int i = 0; i < 4; i++)
#pragma unroll
                for (int j = 0; j < 4; j++) MMA_BF16(d[i * 4 + j], Afh[i], Bfh[j]);
#pragma unroll
            for (int i = 0; i < 4; i++)
#pragma unroll
                for (int j = 0; j < 4; j++) MMA_BF16(d[i * 4 + j], Afl[i], Bfh[j]);
#pragma unroll
            for (int i = 0; i < 4; i++)
#pragma unroll
                for (int j = 0; j < 4; j++) MMA_BF16(d[i * 4 + j], Afh[i], Bfl[j]);
        }
        __syncthreads();
        if (c + 1 < nch) {
            unsigned short* Ah = smu + ((c + 1) & 1) * 12288;
            const int off = lrow * 24 + lks;
#pragma unroll
            for (int j2 = 0; j2 < 4; j2++) {
                float v0 = pa[2 * j2], v1 = pa[2 * j2 + 1];
                unsigned short h0 = bfh(v0), h1 = bfh(v1);
                uint32_t hp = (uint32_t)h0 | ((uint32_t)h1 << 16);
                uint32_t lp = (uint32_t)bfh(v0 - bff(h0)) | ((uint32_t)bfh(v1 - bff(h1)) << 16);
                *(uint32_t*)(Ah + off + 2 * j2) = hp;
                *(uint32_t*)(Ah + 3072 + off + 2 * j2) = lp;
                v0 = pw[2 * j2]; v1 = pw[2 * j2 + 1];
                h0 = bfh(v0); h1 = bfh(v1);
                hp = (uint32_t)h0 | ((uint32_t)h1 << 16);
                lp = (uint32_t)bfh(v0 - bff(h0)) | ((uint32_t)bfh(v1 - bff(h1)) << 16);
                *(uint32_t*)(Ah + 6144 + off + 2 * j2) = hp;
                *(uint32_t*)(Ah + 9216 + off + 2 * j2) = lp;
            }
            __syncthreads();
        }
    }

    const int er = lane >> 2, ec = (lane & 3) * 2;
#pragma unroll
    for (int i = 0; i < 4; i++)
#pragma unroll
        for (int j = 0; j < 4; j++) {
            const float* dd = d[i * 4 + j];
            int gm = m0 + mw + 16 * i + er;
            int gn = n0 + nw + 8 * j + ec;
            float v0 = dd[0], v1 = dd[1], v2 = dd[2], v3 = dd[3];
            if (bias) { float bb0 = bias[gn], bb1 = bias[gn + 1]; v0 += bb0; v1 += bb1; v2 += bb0; v3 += bb1; }
            size_t o1 = (size_t)gm * ldc + gn, o2 = (size_t)(gm + 8) * ldc + gn;
            if (init) {
                float2 i1 = *(const float2*)(init + o1), i2 = *(const float2*)(init + o2);
                v0 += i1.x; v1 += i1.y; v2 += i2.x; v3 += i2.y;
            }
            *(float2*)(C + o1) = make_float2(v0, v1);
            *(float2*)(C + o2) = make_float2(v2, v3);
        }
}

// ---- 64x64 fp32 GEMM body + wrappers ---------------------------------------
struct GP { const float* A; const float* W; const float* bias; float* C;
            int K; int lda; int ldw; int N; int ldc; };

DEVI void gemm_nt_body(float* C, const float* A, const float* W, const float* bias,
                       int K, int lda, int ldw, int ldc, int m0, int n0, int accum) {
    __shared__ float As[16][68];
    __shared__ float Ws[16][68];
    const int tid = threadIdx.x;
    const int lk = tid & 15, lr = tid >> 4;
    const int tx = tid & 15, ty = tid >> 4;
    unsigned long long acc2[4][2] = {};
    for (int k0 = 0; k0 < K; k0 += 16) {
        const int kk = k0 + lk;
        const bool kin = kk < K;
#pragma unroll
        for (int i = 0; i < 4; i++) {
            As[lk][lr + i * 16] = kin ? A[(size_t)(m0 + lr + i * 16) * lda + kk] : 0.f;
            Ws[lk][lr + i * 16] = kin ? W[(size_t)(n0 + lr + i * 16) * ldw + kk] : 0.f;
        }
        __syncthreads();
#pragma unroll
        for (int k = 0; k < 16; k++) {
            float4 av = *(const float4*)&As[k][ty * 4];
            ulonglong2 bv = *(const ulonglong2*)&Ws[k][tx * 4];
            float a_[4] = {av.x, av.y, av.z, av.w};
#pragma unroll
            for (int i = 0; i < 4; i++) {
                unsigned long long ad;
                asm("mov.b64 %0, {%1, %1};" : "=l"(ad) : "r"(__float_as_uint(a_[i])));
                ffma2(acc2[i][0], ad, bv.x);
                ffma2(acc2[i][1], ad, bv.y);
            }
        }
        __syncthreads();
    }
#pragma unroll
    for (int i = 0; i < 4; i++) {
        const int m = m0 + ty * 4 + i;
        float cv[4];
        asm("mov.b64 {%0, %1}, %2;" : "=f"(cv[0]), "=f"(cv[1]) : "l"(acc2[i][0]));
        asm("mov.b64 {%0, %1}, %2;" : "=f"(cv[2]), "=f"(cv[3]) : "l"(acc2[i][1]));
#pragma unroll
        for (int j = 0; j < 4; j++) {
            const int n = n0 + tx * 4 + j;
            float v = cv[j];
            if (bias) v += bias[n];
            size_t o = (size_t)m * ldc + n;
            if (accum) v += C[o];
            C[o] = v;
        }
    }
}

__global__ void __launch_bounds__(256) gemm_nt(
    float* C, const float* A, const float* W, const float* bias,
    int M, int N, int K, int lda, int ldw, int ldc, int accum)
{
    gemm_nt_body(C, A, W, bias, K, lda, ldw, ldc,
                 blockIdx.y << 6, blockIdx.x << 6, accum);
}

__global__ void __launch_bounds__(256) gemm_nt2(GP p0, GP p1)
{
    GP p = blockIdx.z ? p1 : p0;
    int n0 = blockIdx.x << 6;
    if (n0 >= p.N) return;
    gemm_nt_body(p.C, p.A, p.W, p.bias, p.K, p.lda, p.ldw, p.ldc,
                 blockIdx.y << 6, n0, 0);
}

// ---- small kernels (fused, from R14) ----------------------------------------
__global__ void gathers(float* __restrict__ facts, const float* __restrict__ hist,
                        const int* __restrict__ eos,
                        float* __restrict__ q, float* __restrict__ Mt,
                        const float* __restrict__ histq, const int* __restrict__ qlen) {
    int idx = blockIdx.x * blockDim.x + threadIdx.x;
    int b = idx >> 14, s = (idx >> 8) & 63, c = idx & 255;
    int t = eos[b * Sc + s];
    facts[idx] = hist[((size_t)t * Bc + b) * Hd + c];
    if (idx < Bc * Hd) {
        int b2 = idx >> 8, c2 = idx & 255;
        int tq = qlen[b2] - 1;
        tq = tq < 0 ? 0 : (tq > Tqc - 1 ? Tqc - 1 : tq);
        float v = histq[((size_t)tq * Bc + b2) * Hd + c2];
        q[idx] = v;
        Mt[idx] = v;
    }
}
__global__ void pack_all(float* __restrict__ W0, float* __restrict__ Wd,
                         float* __restrict__ w7, float* __restrict__ w8,
                         const float* __restrict__ gW1) {
    int i = blockIdx.x * blockDim.x + threadIdx.x;
    {
        int g = i / 768, k = i % 768;
        int col = (k < 256) ? k : ((k < 512) ? 1024 + (k - 256) : 1536 + (k - 512));
        W0[i] = gW1[(size_t)g * Zc + col];
    }
    if (i < GWc * 2 * Hd) {
        int g = i >> 9, k = i & 511;
        int col = (k < 256) ? 768 + k : 1280 + (k - 256);
        Wd[i] = gW1[(size_t)g * Zc + col];
    }
    if (i < GWc) {
        w7[i] = gW1[(size_t)i * Zc + 1792];
        w8[i] = gW1[(size_t)i * Zc + 1793];
    }
}
__global__ void build_F0(float* __restrict__ F0, const float* __restrict__ facts,
                         const float* __restrict__ q) {
    int idx = blockIdx.x * blockDim.x + threadIdx.x;
    int bs = idx >> 8, c = idx & 255;
    int b = bs >> 6;
    float C = facts[idx];
    float qv = q[b * Hd + c];
    float* dst = F0 + (size_t)bs * (3 * Hd);
    dst[c]          = C;
    dst[Hd + c]     = C * qv;
    dst[2 * Hd + c] = fabsf(C - qv);
}
__global__ void vecmat(float* __restrict__ out, const float* __restrict__ v,
                       const float* __restrict__ Wkh) {
    __shared__ float vs[Hd];
    int b = blockIdx.x, h = threadIdx.x;
    vs[h] = v[b * Hd + h];
    __syncthreads();
    float a = 0.f;
#pragma unroll 8
    for (int k = 0; k < Hd; k++) a += vs[k] * Wkh[k * Hd + h];
    out[b * Hd + h] = a;
}
__global__ void sdots_fq(float* __restrict__ smo, float* __restrict__ sqo,
                         const float* __restrict__ facts, const float* __restrict__ mt,
                         const float* __restrict__ uq, const float* __restrict__ zW,
                         float* __restrict__ Fd, float* __restrict__ qm,
                         const float* __restrict__ q) {
    int bx = blockIdx.x, tid = threadIdx.x;
    if (bx < Bc) {
        __shared__ float vs[Hd];
        __shared__ float um_s[Hd];
        __shared__ float uq_s[Hd];
        int b = bx;
        vs[tid] = mt[b * Hd + tid];
        uq_s[tid] = uq[b * Hd + tid];
        __syncthreads();
        float a = 0.f;
#pragma unroll 8
        for (int k = 0; k < Hd; k++) a += vs[k] * zW[k * Hd + tid];
        um_s[tid] = a;
        __syncthreads();
        int w = tid >> 5, lane = tid & 31;
        for (int s = w; s < Sc; s += 8) {
            const float* C = facts + ((size_t)b * Sc + s) * Hd;
            float a1 = 0.f, a2 = 0.f;
#pragma unroll
            for (int c = lane; c < Hd; c += 32) {
                float cv = C[c];
                a1 += cv * um_s[c];
                a2 += cv * uq_s[c];
            }
#pragma unroll
            for (int o = 16; o; o >>= 1) {
                a1 += __shfl_xor_sync(0xffffffffu, a1, o);
                a2 += __shfl_xor_sync(0xffffffffu, a2, o);
            }
            if (!lane) { smo[b * Sc + s] = a1; sqo[b * Sc + s] = a2; }
        }
    } else {
        int idx = (bx - Bc) * 256 + tid;
        int bs = idx >> 8, c = idx & 255;
        int b = bs >> 6;
        float C = facts[idx];
        float m = mt[b * Hd + c];
        float* dst = Fd + (size_t)bs * (2 * Hd);
        dst[c]      = C * m;
        dst[Hd + c] = fabsf(C - m);
        if (idx < Bc * 512) {
            int b2 = idx >> 9, c2 = idx & 511;
            qm[idx] = (c2 < Hd) ? q[b2 * Hd + c2] : mt[b2 * Hd + c2 - Hd];
        }
    }
}
__global__ void __launch_bounds__(512) att_soft(
    float* __restrict__ Htc, const float* __restrict__ P, const float* __restrict__ cst,
    const float* __restrict__ smv, const float* __restrict__ sqv,
    const float* __restrict__ w7, const float* __restrict__ w8,
    const float* __restrict__ gW2, const float* __restrict__ gb2,
    const float* __restrict__ facts) {
    __shared__ float sa[Sc];
    __shared__ float inv;
    int b = blockIdx.x, tid = threadIdx.x;
    int w = tid >> 5, lane = tid & 31;
    const float* cr = cst + (size_t)b * GWc;
    for (int s = w; s < Sc; s += 16) {
        int wg = b * Sc + s;
        float s1 = smv[wg], s2 = sqv[wg];
        const float* Pr = P + (size_t)wg * GWc;
        float acc = 0.f;
#pragma unroll
        for (int g = lane; g < GWc; g += 32)
            acc += tanhfast(Pr[g] + cr[g] + s1 * w7[g] + s2 * w8[g]) * gW2[g];
#pragma unroll
        for (int o = 16; o; o >>= 1) acc += __shfl_xor_sync(0xffffffffu, acc, o);
        if (!lane) sa[s] = sigf(acc + gb2[0]);
    }
    __syncthreads();
    if (tid == 0) {
        float mx = -1e30f;
        for (int s = 0; s < Sc; s++) mx = fmaxf(mx, sa[s]);
        float sum = 0.f;
        for (int s = 0; s < Sc; s++) { float e = expf(sa[s] - mx); sa[s] = e; sum += e; }
        inv = 1.f / sum;
    }
    __syncthreads();
    if (tid < Hd) {
        float a = 0.f;
#pragma unroll 8
        for (int s = 0; s < Sc; s++) a += facts[((size_t)b * Sc + s) * Hd + tid] * sa[s];
        Htc[b * Hd + tid] = a * inv;
    }
}
__global__ void gru_gate(float* __restrict__ hnew, const float* __restrict__ gi,
                         const float* __restrict__ gh, const float* __restrict__ hold) {
    int idx = blockIdx.x * blockDim.x + threadIdx.x;
    int b = idx >> 8, c = idx & 255;
    size_t o = (size_t)b * H3;
    float r = sigf(gi[o + c] + gh[o + c]);
    float z = sigf(gi[o + 256 + c] + gh[o + 256 + c]);
    float n = tanhfast(gi[o + 512 + c] + r * gh[o + 512 + c]);
    hnew[idx] = (1.f - z) * n + z * hold[idx];
}
__global__ void ysoft_xt(float* __restrict__ xt, const float* __restrict__ h,
                         const float* __restrict__ Wa, const float* __restrict__ q) {
    int b = blockIdx.x, tid = threadIdx.x;
    __shared__ float hb[Hd];
    __shared__ float lg[Vc];
    __shared__ float inv;
    hb[tid] = h[b * Hd + tid];
    __syncthreads();
    if (tid < Vc) {
        const float* w = Wa + (size_t)tid * Hd;
        float a = 0.f;
#pragma unroll 8
        for (int k = 0; k < Hd; k++) a += hb[k] * w[k];
        lg[tid] = a;
    }
    __syncthreads();
    if (tid == 0) {
        float mx = -1e30f;
        for (int v = 0; v < Vc; v++) mx = fmaxf(mx, lg[v]);
        float sum = 0.f;
        for (int v = 0; v < Vc; v++) { float e = expf(lg[v] - mx); lg[v] = e; sum += e; }
        inv = 1.f / sum;
    }
    __syncthreads();
    float* row = xt + (size_t)b * (Vc + Hd);
    if (tid < Vc) row[tid] = lg[tid] * inv;
    row[Vc + tid] = q[b * Hd + tid];
}
__global__ void ysoft(float* __restrict__ out, const float* __restrict__ h,
                      const float* __restrict__ Wa) {
    int b = blockIdx.x, tid = threadIdx.x;
    __shared__ float hb[Hd];
    __shared__ float lg[Vc];
    __shared__ float inv;
    hb[tid] = h[b * Hd + tid];
    __syncthreads();
    if (tid < Vc) {
        const float* w = Wa + (size_t)tid * Hd;
        float a = 0.f;
#pragma unroll 8
        for (int k = 0; k < Hd; k++) a += hb[k] * w[k];
        lg[tid] = a;
    }
    __syncthreads();
    if (tid == 0) {
        float mx = -1e30f;
        for (int v = 0; v < Vc; v++) mx = fmaxf(mx, lg[v]);
        float sum = 0.f;
        for (int v = 0; v < Vc; v++) { float e = expf(lg[v] - mx); lg[v] = e; sum += e; }
        inv = 1.f / sum;
    }
    __syncthreads();
    if (tid < Vc) out[b * Vc + tid] = lg[tid] * inv;
}

extern "C" void kernel_launch(void* const* d_in, const int* in_sizes, int n_in,
                              void* d_out, int out_size) {
    const float* input = (const float*)d_in[0];
    const float* Qin   = (const float*)d_in[1];
    const int*   EOS   = (const int*)d_in[2];
    const int*   qlen  = (const int*)d_in[3];
    const int wo = (n_in >= 28) ? 6 : 4;
    const float* Wih_i = (const float*)d_in[wo + 0];
    const float* Whh_i = (const float*)d_in[wo + 1];
    const float* bih_i = (const float*)d_in[wo + 2];
    const float* bhh_i = (const float*)d_in[wo + 3];
    const float* Wih_q = (const float*)d_in[wo + 4];
    const float* Whh_q = (const float*)d_in[wo + 5];
    const float* bih_q = (const float*)d_in[wo + 6];
    const float* bhh_q = (const float*)d_in[wo + 7];
    const float* zW    = (const float*)d_in[wo + 8];
    const float* gW1   = (const float*)d_in[wo + 9];
    const float* gb1   = (const float*)d_in[wo + 10];
    const float* gW2   = (const float*)d_in[wo + 11];
    const float* gb2   = (const float*)d_in[wo + 12];
    const float* Wih_m = (const float*)d_in[wo + 13];
    const float* Whh_m = (const float*)d_in[wo + 14];
    const float* bih_m = (const float*)d_in[wo + 15];
    const float* bhh_m = (const float*)d_in[wo + 16];
    const float* Wa    = (const float*)d_in[wo + 17];
    const float* Wih_a = (const float*)d_in[wo + 18];
    const float* Whh_a = (const float*)d_in[wo + 19];
    const float* bih_a = (const float*)d_in[wo + 20];
    const float* bhh_a = (const float*)d_in[wo + 21];

    float* base = nullptr;
    cudaGetSymbolAddress((void**)&base, g_buf);
    float* GI_i   = base + O_GI_I;
    float* hist_i = base + O_HIST_I;
    float* GI_q   = base + O_GI_Q;
    float* hist_q = base + O_HIST_Q;
    float* Fd     = base + O_FD;
    float* P      = base + O_P;
    float* facts  = base + O_FACTS;
    float* hA     = base + O_HA;
    float* qv     = base + O_QV;
    float* Mt     = base + O_MT;
    float* uq     = base + O_UQ;
    float* Htc    = base + O_HTC;
    float* qm     = base + O_QM;
    float* cst    = base + O_CST;
    float* smv    = base + O_SM;
    float* sqv    = base + O_SQ;
    float* gib    = base + O_GIB;
    float* ghb    = base + O_GHB;
    float* xt     = base + O_XT;
    float* w7     = base + O_W7;
    float* w8     = base + O_W8;
    float* F0     = base + O_F0;
    float* P0     = base + O_P0;
    float* W0     = base + O_W0;
    float* Wd     = base + O_WD;
    unsigned short* AHI = (unsigned short*)(base + O_AHI);
    unsigned short* ALO = (unsigned short*)(base + O_ALO);
    unsigned short* WHI = (unsigned short*)(base + O_WHI);
    unsigned short* WLO = (unsigned short*)(base + O_WLO);

    cudaFuncSetAttribute(gru_cluster, cudaFuncAttributeMaxDynamicSharedMemorySize, SMEM_GRUC);
    cudaFuncSetAttribute(gemm_mma, cudaFuncAttributeMaxDynamicSharedMemorySize, SMEM_MMA);
    cudaFuncSetAttribute(gemm_mma_pre, cudaFuncAttributeMaxDynamicSharedMemorySize, SMEM_MMA);

    // ---- input GRU ----
    split2<<<(Bc * Tc * Gc / 4 + 255) / 256, 256>>>(AHI, ALO, input, Bc * Tc * Gc / 4);
    split2<<<(H3 * Gc / 4 + 255) / 256, 256>>>(WHI, WLO, Wih_i, H3 * Gc / 4);
    gemm_mma_pre<<<dim3(H3 / 128, (Bc * Tc) / 128), 256, SMEM_MMA>>>(
        GI_i, AHI, ALO, WHI, WLO, bih_i, Bc * Tc, H3, Gc, Gc, Gc, H3);
    gru_cluster<<<128, 256, SMEM_GRUC>>>(GI_i, hist_i, Whh_i, bhh_i, Tc);

    // ---- query GRU ----
    split2<<<(Bc * Tqc * Gc / 4 + 255) / 256, 256>>>(AHI, ALO, Qin, Bc * Tqc * Gc / 4);
    split2<<<(H3 * Gc / 4 + 255) / 256, 256>>>(WHI, WLO, Wih_q, H3 * Gc / 4);
    gemm_mma_pre<<<dim3(H3 / 128, (Bc * Tqc) / 128), 256, SMEM_MMA>>>(
        GI_q, AHI, ALO, WHI, WLO, bih_q, Bc * Tqc, H3, Gc, Gc, Gc, H3);
    gru_cluster<<<128, 256, SMEM_GRUC>>>(GI_q, hist_q, Whh_q, bhh_q, Tqc);

    // ---- gathers + depth-invariant precompute ----
    gathers<<<(Bc * Sc * Hd) / 256, 256>>>(facts, hist_i, EOS, qv, Mt, hist_q, qlen);
    pack_all<<<(GWc * 3 * Hd) / 256, 256>>>(W0, Wd, w7, w8, gW1);
    vecmat<<<Bc, Hd>>>(uq, qv, zW);
    build_F0<<<(Bc * Sc * Hd) / 256, 256>>>(F0, facts, qv);
    gemm_mma<<<dim3(GWc / 128, (Bc * Sc) / 128), 256, SMEM_MMA>>>(
        P0, F0, W0, nullptr, nullptr, Bc * Sc, GWc, 3 * Hd, 3 * Hd, 3 * Hd, GWc);

    // ---- episodic memory: m_depth = 3 ----
    for (int d = 0; d < 3; d++) {
        sdots_fq<<<Bc + (Bc * Sc * Hd) / 256, 256>>>(
            smv, sqv, facts, Mt, uq, zW, Fd, qm, qv);
        gemm_mma<<<dim3(GWc / 128, (Bc * Sc) / 128), 256, SMEM_MMA>>>(
            P, Fd, Wd, nullptr, P0, Bc * Sc, GWc, 2 * Hd, 2 * Hd, 2 * Hd, GWc);
        GP pc = {qm, gW1 + 256, gb1, cst, 512, 512, Zc, GWc, GWc};
        GP ph = {Mt,  Whh_m, bhh_m, ghb, Hd, Hd, Hd, H3, H3};
        gemm_nt2<<<dim3(H3 / 64, Bc / 64, 2), 256>>>(pc, ph);
        att_soft<<<Bc, 512>>>(Htc, P, cst, smv, sqv, w7, w8, gW2, gb2, facts);
        gemm_nt<<<dim3(H3 / 64, Bc / 64), 256>>>(
            gib, Htc, Wih_m, bih_m, Bc, H3, Hd, Hd, Hd, H3, 0);
        gru_gate<<<(Bc * Hd) / 256, 256>>>(Mt, gib, ghb, Mt);
    }

    // ---- answer module: a_len = 1 ----
    ysoft_xt<<<Bc, Hd>>>(xt, Mt, Wa, qv);
    {
        GP pg = {xt, Wih_a, bih_a, gib, Vc + Hd, Vc + Hd, Vc + Hd, H3, H3};
        GP ph = {Mt, Whh_a, bhh_a, ghb, Hd, Hd, Hd, H3, H3};
        gemm_nt2<<<dim3(H3 / 64, Bc / 64, 2), 256>>>(pg, ph);
    }
    gru_gate<<<(Bc * Hd) / 256, 256>>>(hA, gib, ghb, Mt);
    ysoft<<<Bc, Hd>>>((float*)d_out, hA, Wa);
}

// round 16
// speedup vs baseline: 1.1362x; 1.1362x over previous
#include <cuda_runtime.h>
#include <cuda_bf16.h>
#include <math.h>
#include <stdint.h>

#define DEVI static __device__ __forceinline__

constexpr int Bc = 128, Tc = 512, Tqc = 32, Sc = 64, Gc = 300, Hd = 256;
constexpr int GWc = 512, Vc = 159, H3 = 768, Zc = 1794;

constexpr size_t O_GI_I   = 0;
constexpr size_t O_HIST_I = O_GI_I   + (size_t)Bc * Tc * H3;
constexpr size_t O_GI_Q   = O_HIST_I + (size_t)Tc * Bc * Hd;
constexpr size_t O_HIST_Q = O_GI_Q   + (size_t)Bc * Tqc * H3;
constexpr size_t O_FD     = O_HIST_Q + (size_t)Tqc * Bc * Hd;
constexpr size_t O_P      = O_FD     + (size_t)Bc * Sc * 4 * Hd;
constexpr size_t O_FACTS  = O_P      + (size_t)Bc * Sc * GWc;
constexpr size_t O_HA     = O_FACTS  + (size_t)Bc * Sc * Hd;
constexpr size_t O_QV     = O_HA  + (size_t)Bc * Hd;
constexpr size_t O_MT     = O_QV  + (size_t)Bc * Hd;
constexpr size_t O_UQ     = O_MT  + (size_t)Bc * Hd;
constexpr size_t O_HTC    = O_UQ  + (size_t)Bc * Hd;
constexpr size_t O_QM     = O_HTC + (size_t)Bc * Hd;
constexpr size_t O_CST    = O_QM  + (size_t)Bc * 2 * Hd;
constexpr size_t O_SM     = O_CST + (size_t)Bc * GWc;
constexpr size_t O_SQ     = O_SM  + (size_t)Bc * Sc;
constexpr size_t O_GIB    = O_SQ  + (size_t)Bc * Sc;
constexpr size_t O_GHB    = O_GIB + (size_t)Bc * H3;
constexpr size_t O_XT     = O_GHB + (size_t)Bc * H3;
constexpr size_t O_W7     = O_XT  + (size_t)Bc * (Vc + Hd);
constexpr size_t O_W8     = O_W7  + (size_t)GWc;
constexpr size_t O_F0     = O_W8  + (size_t)GWc;
constexpr size_t O_P0     = O_F0  + (size_t)Bc * Sc * 3 * Hd;
constexpr size_t O_W0     = O_P0  + (size_t)Bc * Sc * GWc;
constexpr size_t O_WD     = O_W0  + (size_t)GWc * 3 * Hd;
constexpr size_t G_TOTAL  = O_WD  + (size_t)GWc * 2 * Hd;

__device__ float g_buf[G_TOTAL];

DEVI float sigf(float x) { return 1.f / (1.f + __expf(-x)); }
DEVI float tanhfast(float x) {
    float ax = fabsf(x);
    float e = __expf(-2.f * ax);
    return copysignf((1.f - e) / (1.f + e), x);
}
DEVI void ffma2(unsigned long long& acc, unsigned long long a, unsigned long long b) {
    asm("fma.rn.f32x2 %0, %1, %2, %0;" : "+l"(acc) : "l"(a), "l"(b));
}
DEVI float hsum2(unsigned long long a) {
    float lo, hi;
    asm("mov.b64 {%0, %1}, %2;" : "=f"(lo), "=f"(hi) : "l"(a));
    return lo + hi;
}
DEVI uint32_t s2u(const void* p) {
    uint32_t a;
    asm("{ .reg .u64 t; cvta.to.shared.u64 t, %1; cvt.u32.u64 %0, t; }" : "=r"(a) : "l"(p));
    return a;
}
DEVI void stclu(uint32_t laddr, uint32_t rk, float v) {
    uint32_t ra;
    asm("mapa.shared::cluster.u32 %0, %1, %2;" : "=r"(ra) : "r"(laddr), "r"(rk));
    asm volatile("st.shared::cluster.f32 [%0], %1;" :: "r"(ra), "f"(v) : "memory");
}

#define LDM4(r, addr) \
    asm volatile("ldmatrix.sync.aligned.m8n8.x4.shared.b16 {%0,%1,%2,%3},[%4];" \
        : "=r"((r)[0]), "=r"((r)[1]), "=r"((r)[2]), "=r"((r)[3]) : "r"(addr))
#define MMA_BF16(d, a, b) \
    asm volatile("mma.sync.aligned.m16n8k16.row.col.f32.bf16.bf16.f32 " \
        "{%0,%1,%2,%3},{%4,%5,%6,%7},{%8,%9},{%0,%1,%2,%3};" \
        : "+f"((d)[0]), "+f"((d)[1]), "+f"((d)[2]), "+f"((d)[3]) \
        : "r"((a)[0]), "r"((a)[1]), "r"((a)[2]), "r"((a)[3]), "r"((b)[0]), "r"((b)[1]))

#define LOAD8(dst, Row, kb, Kv) do { \
    if ((kb) + 8 <= (Kv)) { \
        float4 t0_ = *(const float4*)((Row) + (kb)); \
        float4 t1_ = *(const float4*)((Row) + (kb) + 4); \
        (dst)[0]=t0_.x;(dst)[1]=t0_.y;(dst)[2]=t0_.z;(dst)[3]=t0_.w; \
        (dst)[4]=t1_.x;(dst)[5]=t1_.y;(dst)[6]=t1_.z;(dst)[7]=t1_.w; \
    } else { \
        _Pragma("unroll") for (int j_ = 0; j_ < 8; j_++) { \
            int k_ = (kb) + j_; (dst)[j_] = (k_ < (Kv)) ? (Row)[k_] : 0.f; } \
    } \
} while (0)

DEVI unsigned short bfh(float v) { return __bfloat16_as_ushort(__float2bfloat16(v)); }
DEVI float bff(unsigned short u) { return __bfloat162float(__ushort_as_bfloat16(u)); }

// ---- cluster-resident GRU (R14 + one extra cached W row) -------------------
constexpr int WPF = 260;
constexpr int SMW = 192 * WPF;
constexpr int SMH = 2 * 4 * WPF;
constexpr int SMG = 2 * 768;
constexpr int SMEM_GRUC = (SMW + SMH + SMG) * 4;

__global__ void __launch_bounds__(256, 1) __cluster_dims__(4, 1, 1)
gru_cluster(const float* __restrict__ GI, float* __restrict__ hist,
            const float* __restrict__ Whh, const float* __restrict__ bhh, int T)
{
    extern __shared__ float smf[];
    float* Wsm  = smf;
    float* hbuf = Wsm + SMW;
    float* gsm  = hbuf + SMH;
    const int tid = threadIdx.x;
    uint32_t rank; asm("mov.u32 %0, %%cluster_ctarank;" : "=r"(rank));
    const int b0 = (blockIdx.x >> 2) * 4;
    const int c0 = (int)rank * 64;

    for (int i = tid; i < 192 * 64; i += 256) {
        int r = i >> 6, f4 = i & 63;
        int g = r >> 6, cl = r & 63;
        int sw = f4 ^ ((f4 >> 3) & 7);
        ((float4*)(Wsm + r * WPF))[sw] =
            ((const float4*)(Whh + (size_t)(g * 256 + c0 + cl) * 256))[f4];
    }
    for (int i = tid; i < SMH; i += 256) hbuf[i] = 0.f;

    size_t gioff[3]; int gis[3];
#pragma unroll
    for (int i = 0; i < 3; i++) {
        int j = tid + i * 256;
        int b = j / 192, col = j % 192;
        gioff[i] = ((size_t)(b0 + b) * T) * H3 + (size_t)((col >> 6) * 256 + c0 + (col & 63));
        gis[i] = j;
    }
    float gp[3];
#pragma unroll
    for (int i = 0; i < 3; i++) gp[i] = __ldcg(GI + gioff[i]);
#pragma unroll
    for (int i = 0; i < 3; i++) gsm[gis[i]] = gp[i];
    __syncthreads();

    const int ks = tid & 7, rt = tid >> 3;
    const int cl0 = rt, cl1 = rt + 32;
    ulonglong2 wc0[8], wc1[8], wc2[8];
#pragma unroll
    for (int j = 0; j < 8; j++) {
        int sw4 = ((ks * 8 + j) ^ ks) * 4;
        wc0[j] = *(const ulonglong2*)(Wsm + cl0 * WPF + sw4);
        wc1[j] = *(const ulonglong2*)(Wsm + cl1 * WPF + sw4);
        wc2[j] = *(const ulonglong2*)(Wsm + (64 + cl0) * WPF + sw4);
    }
    const int w2i = ks >> 2, b1b = (ks >> 1) & 1, b0b = ks & 1;
    const int b_e = 2 * b1b + b0b;
    const int cl_e = w2i ? cl1 : cl0;
    const int cg_e = c0 + cl_e;
    const int f4c_e = cg_e >> 2;
    const int swc_e = (f4c_e ^ ((f4c_e >> 3) & 7)) * 4 + (cg_e & 3);
    const float bhr = bhh[cg_e], bhz = bhh[256 + cg_e], bhn = bhh[512 + cg_e];
    const int go_r = b_e * 192 + cl_e;
    const uint32_t hb_u = s2u(hbuf);
    int cur = 0;

    for (int t = 0; t < T; t++) {
        const float* hc = hbuf + cur * (4 * WPF);
        if (t + 1 < T) {
#pragma unroll
            for (int i = 0; i < 3; i++)
                gp[i] = __ldcg(GI + gioff[i] + (size_t)(t + 1) * H3);
        }
        unsigned long long acc[24];
#pragma unroll
        for (int i = 0; i < 24; i++) acc[i] = 0ull;
#pragma unroll
        for (int j = 0; j < 8; j++) {
            int sw4 = ((ks * 8 + j) ^ ks) * 4;
            ulonglong2 hv[4];
#pragma unroll
            for (int b = 0; b < 4; b++) hv[b] = *(const ulonglong2*)(hc + b * WPF + sw4);
            ulonglong2 w3 = *(const ulonglong2*)(Wsm + (64 + cl1) * WPF + sw4);
            ulonglong2 w4 = *(const ulonglong2*)(Wsm + (128 + cl0) * WPF + sw4);
            ulonglong2 w5 = *(const ulonglong2*)(Wsm + (128 + cl1) * WPF + sw4);
#pragma unroll
            for (int b = 0; b < 4; b++) {
                ffma2(acc[0 * 4 + b], hv[b].x, wc0[j].x); ffma2(acc[0 * 4 + b], hv[b].y, wc0[j].y);
                ffma2(acc[1 * 4 + b], hv[b].x, wc1[j].x); ffma2(acc[1 * 4 + b], hv[b].y, wc1[j].y);
                ffma2(acc[2 * 4 + b], hv[b].x, wc2[j].x); ffma2(acc[2 * 4 + b], hv[b].y, wc2[j].y);
                ffma2(acc[3 * 4 + b], hv[b].x, w3.x);     ffma2(acc[3 * 4 + b], hv[b].y, w3.y);
                ffma2(acc[4 * 4 + b], hv[b].x, w4.x);     ffma2(acc[4 * 4 + b], hv[b].y, w4.y);
                ffma2(acc[5 * 4 + b], hv[b].x, w5.x);     ffma2(acc[5 * 4 + b], hv[b].y, w5.y);
            }
        }
        float s[24];
#pragma unroll
        for (int i = 0; i < 24; i++) s[i] = hsum2(acc[i]);

        float t12[12];
#pragma unroll
        for (int g = 0; g < 3; g++)
#pragma unroll
            for (int b = 0; b < 4; b++) {
                float mine  = w2i ? s[(2 * g + 1) * 4 + b] : s[(2 * g) * 4 + b];
                float other = w2i ? s[(2 * g) * 4 + b]     : s[(2 * g + 1) * 4 + b];
                t12[g * 4 + b] = mine + __shfl_xor_sync(0xffffffffu, other, 4);
            }
        float u6[6];
#pragma unroll
        for (int g = 0; g < 3; g++)
#pragma unroll
            for (int bl = 0; bl < 2; bl++) {
                float mine  = b1b ? t12[g * 4 + 2 + bl] : t12[g * 4 + bl];
                float other = b1b ? t12[g * 4 + bl]     : t12[g * 4 + 2 + bl];
                u6[g * 2 + bl] = mine + __shfl_xor_sync(0xffffffffu, other, 2);
            }
        float v3[3];
#pragma unroll
        for (int g = 0; g < 3; g++) {
            float mine  = b0b ? u6[g * 2 + 1] : u6[g * 2];
            float other = b0b ? u6[g * 2]     : u6[g * 2 + 1];
            v3[g] = mine + __shfl_xor_sync(0xffffffffu, other, 1);
        }

        {
            const float* gb = gsm + (t & 1) * 768;
            float r = sigf(gb[go_r] + v3[0] + bhr);
            float z = sigf(gb[go_r + 64] + v3[1] + bhz);
            float n = tanhfast(gb[go_r + 128] + r * (v3[2] + bhn));
            float ho = hc[b_e * WPF + swc_e];
            float hv = (1.f - z) * n + z * ho;
            hist[((size_t)t * Bc + b0 + b_e) * Hd + cg_e] = hv;
            uint32_t la = hb_u + (uint32_t)((((cur ^ 1) * 4 + b_e) * WPF + swc_e) * 4);
#pragma unroll
            for (uint32_t rk = 0; rk < 4; rk++) stclu(la, rk, hv);
        }
        asm volatile("barrier.cluster.arrive.aligned;" ::: "memory");
        if (t + 1 < T) {
            float* gd = gsm + ((t + 1) & 1) * 768;
#pragma unroll
            for (int i = 0; i < 3; i++) gd[gis[i]] = gp[i];
        }
        asm volatile("barrier.cluster.wait.aligned;" ::: "memory");
        cur ^= 1;
    }
}

// ---- gemm_mma: split-bf16 tensor-core GEMM (unchanged, passing) ------------
constexpr int SMEM_MMA = 2 * 4 * 128 * 24 * 2;

__global__ void __launch_bounds__(256) gemm_mma(
    float* __restrict__ C, const float* __restrict__ A, const float* __restrict__ W,
    const float* __restrict__ bias, const float* __restrict__ init,
    int M, int N, int K, int lda, int ldw, int ldc)
{
    extern __shared__ unsigned short smu[];
    const int tid = threadIdx.x;
    const int warp = tid >> 5, lane = tid & 31;
    const int m0 = blockIdx.y << 7, n0 = blockIdx.x << 7;
    const int mw = (warp >> 2) * 64, nw = (warp & 3) * 32;
    const int lrow = tid >> 1, lks = (tid & 1) * 8;
    const float* Arow = A + (size_t)(m0 + lrow) * lda;
    const float* Wrow = W + (size_t)(n0 + lrow) * ldw;
    const uint32_t base_u = s2u(smu);

    float d[16][4];
#pragma unroll
    for (int i = 0; i < 16; i++)
#pragma unroll
        for (int j = 0; j < 4; j++) d[i][j] = 0.f;

    const int nch = (K + 15) >> 4;
    float pa[8], pw[8];

    LOAD8(pa, Arow, lks, K);
    LOAD8(pw, Wrow, lks, K);
    {
        unsigned short* Ah = smu;
        const int off = lrow * 24 + lks;
#pragma unroll
        for (int j2 = 0; j2 < 4; j2++) {
            float v0 = pa[2 * j2], v1 = pa[2 * j2 + 1];
            unsigned short h0 = bfh(v0), h1 = bfh(v1);
            uint32_t hp = (uint32_t)h0 | ((uint32_t)h1 << 16);
            uint32_t lp = (uint32_t)bfh(v0 - bff(h0)) | ((uint32_t)bfh(v1 - bff(h1)) << 16);
            *(uint32_t*)(Ah + off + 2 * j2) = hp;
            *(uint32_t*)(Ah + 3072 + off + 2 * j2) = lp;
            v0 = pw[2 * j2]; v1 = pw[2 * j2 + 1];
            h0 = bfh(v0); h1 = bfh(v1);
            hp = (uint32_t)h0 | ((uint32_t)h1 << 16);
            lp = (uint32_t)bfh(v0 - bff(h0)) | ((uint32_t)bfh(v1 - bff(h1)) << 16);
            *(uint32_t*)(Ah + 6144 + off + 2 * j2) = hp;
            *(uint32_t*)(Ah + 9216 + off + 2 * j2) = lp;
        }
    }
    __syncthreads();

    const int lr16 = lane & 15, kh = (lane >> 4) * 8;
    for (int c = 0; c < nch; c++) {
        if (c + 1 < nch) {
            const int kb = (c + 1) * 16 + lks;
            LOAD8(pa, Arow, kb, K);
            LOAD8(pw, Wrow, kb, K);
        }
        {
            const uint32_t bu = base_u + (uint32_t)((c & 1) * 24576);
            uint32_t Afh[4][4], Afl[4][4], Bfh[4][2], Bfl[4][2];
#pragma unroll
            for (int i = 0; i < 4; i++) {
                uint32_t ad = bu + (uint32_t)(((mw + 16 * i + lr16) * 24 + kh) * 2);
                LDM4(Afh[i], ad);
                LDM4(Afl[i], ad + 6144);
            }
#pragma unroll
            for (int jj = 0; jj < 2; jj++) {
                uint32_t ad = bu + 12288 + (uint32_t)(((nw + 16 * jj + lr16) * 24 + kh) * 2);
                uint32_t r[4];
                LDM4(r, ad);
                Bfh[2 * jj][0] = r[0]; Bfh[2 * jj][1] = r[2];
                Bfh[2 * jj + 1][0] = r[1]; Bfh[2 * jj + 1][1] = r[3];
                LDM4(r, ad + 6144);
                Bfl[2 * jj][0] = r[0]; Bfl[2 * jj][1] = r[2];
                Bfl[2 * jj + 1][0] = r[1]; Bfl[2 * jj + 1][1] = r[3];
            }
#pragma unroll
            for (int i = 0; i < 4; i++)
#pragma unroll
                for (int j = 0; j < 4; j++) MMA_BF16(d[i * 4 + j], Afh[i], Bfh[j]);
#pragma unroll
            for (int i = 0; i < 4; i++)
#pragma unroll
                for (int j = 0; j < 4; j++) MMA_BF16(d[i * 4 + j], Afl[i], Bfh[j]);
#pragma unroll
            for (int i = 0; i < 4; i++)
#pragma unroll
                for (int j = 0; j < 4; j++) MMA_BF16(d[i * 4 + j], Afh[i], Bfl[j]);
        }
        __syncthreads();
        if (c + 1 < nch) {
            unsigned short* Ah = smu + ((c + 1) & 1) * 12288;
            const int off = lrow * 24 + lks;
#pragma unroll
            for (int j2 = 0; j2 < 4; j2++) {
                float v0 = pa[2 * j2], v1 = pa[2 * j2 + 1];
                unsigned short h0 = bfh(v0), h1 = bfh(v1);
                uint32_t hp = (uint32_t)h0 | ((uint32_t)h1 << 16);
                uint32_t lp = (uint32_t)bfh(v0 - bff(h0)) | ((uint32_t)bfh(v1 - bff(h1)) << 16);
                *(uint32_t*)(Ah + off + 2 * j2) = hp;
                *(uint32_t*)(Ah + 3072 + off + 2 * j2) = lp;
                v0 = pw[2 * j2]; v1 = pw[2 * j2 + 1];
                h0 = bfh(v0); h1 = bfh(v1);
                hp = (uint32_t)h0 | ((uint32_t)h1 << 16);
                lp = (uint32_t)bfh(v0 - bff(h0)) | ((uint32_t)bfh(v1 - bff(h1)) << 16);
                *(uint32_t*)(Ah + 6144 + off + 2 * j2) = hp;
                *(uint32_t*)(Ah + 9216 + off + 2 * j2) = lp;
            }
            __syncthreads();
        }
    }

    const int er = lane >> 2, ec = (lane & 3) * 2;
#pragma unroll
    for (int i = 0; i < 4; i++)
#pragma unroll
        for (int j = 0; j < 4; j++) {
            const float* dd = d[i * 4 + j];
            int gm = m0 + mw + 16 * i + er;
            int gn = n0 + nw + 8 * j + ec;
            float v0 = dd[0], v1 = dd[1], v2 = dd[2], v3 = dd[3];
            if (bias) { float bb0 = bias[gn], bb1 = bias[gn + 1]; v0 += bb0; v1 += bb1; v2 += bb0; v3 += bb1; }
            size_t o1 = (size_t)gm * ldc + gn, o2 = (size_t)(gm + 8) * ldc + gn;
            if (init) {
                float2 i1 = *(const float2*)(init + o1), i2 = *(const float2*)(init + o2);
                v0 += i1.x; v1 += i1.y; v2 += i2.x; v3 += i2.y;
            }
            *(float2*)(C + o1) = make_float2(v0, v1);
            *(float2*)(C + o2) = make_float2(v2, v3);
        }
}

// ---- 64x64 fp32 GEMM body + wrappers ---------------------------------------
struct GP { const float* A; const float* W; const float* bias; float* C;
            int K; int lda; int ldw; int N; int ldc; };

DEVI void gemm_nt_body(float* C, const float* A, const float* W, const float* bias,
                       int K, int lda, int ldw, int ldc, int m0, int n0, int accum) {
    __shared__ float As[16][68];
    __shared__ float Ws[16][68];
    const int tid = threadIdx.x;
    const int lk = tid & 15, lr = tid >> 4;
    const int tx = tid & 15, ty = tid >> 4;
    unsigned long long acc2[4][2] = {};
    for (int k0 = 0; k0 < K; k0 += 16) {
        const int kk = k0 + lk;
        const bool kin = kk < K;
#pragma unroll
        for (int i = 0; i < 4; i++) {
            As[lk][lr + i * 16] = kin ? A[(size_t)(m0 + lr + i * 16) * lda + kk] : 0.f;
            Ws[lk][lr + i * 16] = kin ? W[(size_t)(n0 + lr + i * 16) * ldw + kk] : 0.f;
        }
        __syncthreads();
#pragma unroll
        for (int k = 0; k < 16; k++) {
            float4 av = *(const float4*)&As[k][ty * 4];
            ulonglong2 bv = *(const ulonglong2*)&Ws[k][tx * 4];
            float a_[4] = {av.x, av.y, av.z, av.w};
#pragma unroll
            for (int i = 0; i < 4; i++) {
                unsigned long long ad;
                asm("mov.b64 %0, {%1, %1};" : "=l"(ad) : "r"(__float_as_uint(a_[i])));
                ffma2(acc2[i][0], ad, bv.x);
                ffma2(acc2[i][1], ad, bv.y);
            }
        }
        __syncthreads();
    }
#pragma unroll
    for (int i = 0; i < 4; i++) {
        const int m = m0 + ty * 4 + i;
        float cv[4];
        asm("mov.b64 {%0, %1}, %2;" : "=f"(cv[0]), "=f"(cv[1]) : "l"(acc2[i][0]));
        asm("mov.b64 {%0, %1}, %2;" : "=f"(cv[2]), "=f"(cv[3]) : "l"(acc2[i][1]));
#pragma unroll
        for (int j = 0; j < 4; j++) {
            const int n = n0 + tx * 4 + j;
            float v = cv[j];
            if (bias) v += bias[n];
            size_t o = (size_t)m * ldc + n;
            if (accum) v += C[o];
            C[o] = v;
        }
    }
}

__global__ void __launch_bounds__(256) gemm_nt(
    float* C, const float* A, const float* W, const float* bias,
    int M, int N, int K, int lda, int ldw, int ldc, int accum)
{
    gemm_nt_body(C, A, W, bias, K, lda, ldw, ldc,
                 blockIdx.y << 6, blockIdx.x << 6, accum);
}

__global__ void __launch_bounds__(256) gemm_nt2(GP p0, GP p1)
{
    GP p = blockIdx.z ? p1 : p0;
    int n0 = blockIdx.x << 6;
    if (n0 >= p.N) return;
    gemm_nt_body(p.C, p.A, p.W, p.bias, p.K, p.lda, p.ldw, p.ldc,
                 blockIdx.y << 6, n0, 0);
}

// ---- small kernels (fused, from R14) ----------------------------------------
__global__ void gathers(float* __restrict__ facts, const float* __restrict__ hist,
                        const int* __restrict__ eos,
                        float* __restrict__ q, float* __restrict__ Mt,
                        const float* __restrict__ histq, const int* __restrict__ qlen) {
    int idx = blockIdx.x * blockDim.x + threadIdx.x;
    int b = idx >> 14, s = (idx >> 8) & 63, c = idx & 255;
    int t = eos[b * Sc + s];
    facts[idx] = hist[((size_t)t * Bc + b) * Hd + c];
    if (idx < Bc * Hd) {
        int b2 = idx >> 8, c2 = idx & 255;
        int tq = qlen[b2] - 1;
        tq = tq < 0 ? 0 : (tq > Tqc - 1 ? Tqc - 1 : tq);
        float v = histq[((size_t)tq * Bc + b2) * Hd + c2];
        q[idx] = v;
        Mt[idx] = v;
    }
}
__global__ void pack_all(float* __restrict__ W0, float* __restrict__ Wd,
                         float* __restrict__ w7, float* __restrict__ w8,
                         const float* __restrict__ gW1) {
    int i = blockIdx.x * blockDim.x + threadIdx.x;
    {
        int g = i / 768, k = i % 768;
        int col = (k < 256) ? k : ((k < 512) ? 1024 + (k - 256) : 1536 + (k - 512));
        W0[i] = gW1[(size_t)g * Zc + col];
    }
    if (i < GWc * 2 * Hd) {
        int g = i >> 9, k = i & 511;
        int col = (k < 256) ? 768 + k : 1280 + (k - 256);
        Wd[i] = gW1[(size_t)g * Zc + col];
    }
    if (i < GWc) {
        w7[i] = gW1[(size_t)i * Zc + 1792];
        w8[i] = gW1[(size_t)i * Zc + 1793];
    }
}
__global__ void build_F0(float* __restrict__ F0, const float* __restrict__ facts,
                         const float* __restrict__ q) {
    int idx = blockIdx.x * blockDim.x + threadIdx.x;
    int bs = idx >> 8, c = idx & 255;
    int b = bs >> 6;
    float C = facts[idx];
    float qv = q[b * Hd + c];
    float* dst = F0 + (size_t)bs * (3 * Hd);
    dst[c]          = C;
    dst[Hd + c]     = C * qv;
    dst[2 * Hd + c] = fabsf(C - qv);
}
__global__ void vecmat(float* __restrict__ out, const float* __restrict__ v,
                       const float* __restrict__ Wkh) {
    __shared__ float vs[Hd];
    int b = blockIdx.x, h = threadIdx.x;
    vs[h] = v[b * Hd + h];
    __syncthreads();
    float a = 0.f;
#pragma unroll 8
    for (int k = 0; k < Hd; k++) a += vs[k] * Wkh[k * Hd + h];
    out[b * Hd + h] = a;
}
__global__ void sdots_fq(float* __restrict__ smo, float* __restrict__ sqo,
                         const float* __restrict__ facts, const float* __restrict__ mt,
                         const float* __restrict__ uq, const float* __restrict__ zW,
                         float* __restrict__ Fd, float* __restrict__ qm,
                         const float* __restrict__ q) {
    int bx = blockIdx.x, tid = threadIdx.x;
    if (bx < Bc) {
        __shared__ float vs[Hd];
        __shared__ float um_s[Hd];
        __shared__ float uq_s[Hd];
        int b = bx;
        vs[tid] = mt[b * Hd + tid];
        uq_s[tid] = uq[b * Hd + tid];
        __syncthreads();
        float a = 0.f;
#pragma unroll 8
        for (int k = 0; k < Hd; k++) a += vs[k] * zW[k * Hd + tid];
        um_s[tid] = a;
        __syncthreads();
        int w = tid >> 5, lane = tid & 31;
        for (int s = w; s < Sc; s += 8) {
            const float* C = facts + ((size_t)b * Sc + s) * Hd;
            float a1 = 0.f, a2 = 0.f;
#pragma unroll
            for (int c = lane; c < Hd; c += 32) {
                float cv = C[c];
                a1 += cv * um_s[c];
                a2 += cv * uq_s[c];
            }
#pragma unroll
            for (int o = 16; o; o >>= 1) {
                a1 += __shfl_xor_sync(0xffffffffu, a1, o);
                a2 += __shfl_xor_sync(0xffffffffu, a2, o);
            }
            if (!lane) { smo[b * Sc + s] = a1; sqo[b * Sc + s] = a2; }
        }
    } else {
        int idx = (bx - Bc) * 256 + tid;
        int bs = idx >> 8, c = idx & 255;
        int b = bs >> 6;
        float C = facts[idx];
        float m = mt[b * Hd + c];
        float* dst = Fd + (size_t)bs * (2 * Hd);
        dst[c]      = C * m;
        dst[Hd + c] = fabsf(C - m);
        if (idx < Bc * 512) {
            int b2 = idx >> 9, c2 = idx & 511;
            qm[idx] = (c2 < Hd) ? q[b2 * Hd + c2] : mt[b2 * Hd + c2 - Hd];
        }
    }
}
__global__ void __launch_bounds__(512) att_soft(
    float* __restrict__ Htc, const float* __restrict__ P, const float* __restrict__ cst,
    const float* __restrict__ smv, const float* __restrict__ sqv,
    const float* __restrict__ w7, const float* __restrict__ w8,
    const float* __restrict__ gW2, const float* __restrict__ gb2,
    const float* __restrict__ facts) {
    __shared__ float sa[Sc];
    __shared__ float inv;
    int b = blockIdx.x, tid = threadIdx.x;
    int w = tid >> 5, lane = tid & 31;
    const float* cr = cst + (size_t)b * GWc;
    for (int s = w; s < Sc; s += 16) {
        int wg = b * Sc + s;
        float s1 = smv[wg], s2 = sqv[wg];
        const float* Pr = P + (size_t)wg * GWc;
        float acc = 0.f;
#pragma unroll
        for (int g = lane; g < GWc; g += 32)
            acc += tanhfast(Pr[g] + cr[g] + s1 * w7[g] + s2 * w8[g]) * gW2[g];
#pragma unroll
        for (int o = 16; o; o >>= 1) acc += __shfl_xor_sync(0xffffffffu, acc, o);
        if (!lane) sa[s] = sigf(acc + gb2[0]);
    }
    __syncthreads();
    if (tid == 0) {
        float mx = -1e30f;
        for (int s = 0; s < Sc; s++) mx = fmaxf(mx, sa[s]);
        float sum = 0.f;
        for (int s = 0; s < Sc; s++) { float e = expf(sa[s] - mx); sa[s] = e; sum += e; }
        inv = 1.f / sum;
    }
    __syncthreads();
    if (tid < Hd) {
        float a = 0.f;
#pragma unroll 8
        for (int s = 0; s < Sc; s++) a += facts[((size_t)b * Sc + s) * Hd + tid] * sa[s];
        Htc[b * Hd + tid] = a * inv;
    }
}
__global__ void gru_gate(float* __restrict__ hnew, const float* __restrict__ gi,
                         const float* __restrict__ gh, const float* __restrict__ hold) {
    int idx = blockIdx.x * blockDim.x + threadIdx.x;
    int b = idx >> 8, c = idx & 255;
    size_t o = (size_t)b * H3;
    float r = sigf(gi[o + c] + gh[o + c]);
    float z = sigf(gi[o + 256 + c] + gh[o + 256 + c]);
    float n = tanhfast(gi[o + 512 + c] + r * gh[o + 512 + c]);
    hnew[idx] = (1.f - z) * n + z * hold[idx];
}
__global__ void ysoft_xt(float* __restrict__ xt, const float* __restrict__ h,
                         const float* __restrict__ Wa, const float* __restrict__ q) {
    int b = blockIdx.x, tid = threadIdx.x;
    __shared__ float hb[Hd];
    __shared__ float lg[Vc];
    __shared__ float inv;
    hb[tid] = h[b * Hd + tid];
    __syncthreads();
    if (tid < Vc) {
        const float* w = Wa + (size_t)tid * Hd;
        float a = 0.f;
#pragma unroll 8
        for (int k = 0; k < Hd; k++) a += hb[k] * w[k];
        lg[tid] = a;
    }
    __syncthreads();
    if (tid == 0) {
        float mx = -1e30f;
        for (int v = 0; v < Vc; v++) mx = fmaxf(mx, lg[v]);
        float sum = 0.f;
        for (int v = 0; v < Vc; v++) { float e = expf(lg[v] - mx); lg[v] = e; sum += e; }
        inv = 1.f / sum;
    }
    __syncthreads();
    float* row = xt + (size_t)b * (Vc + Hd);
    if (tid < Vc) row[tid] = lg[tid] * inv;
    row[Vc + tid] = q[b * Hd + tid];
}
__global__ void ysoft(float* __restrict__ out, const float* __restrict__ h,
                      const float* __restrict__ Wa) {
    int b = blockIdx.x, tid = threadIdx.x;
    __shared__ float hb[Hd];
    __shared__ float lg[Vc];
    __shared__ float inv;
    hb[tid] = h[b * Hd + tid];
    __syncthreads();
    if (tid < Vc) {
        const float* w = Wa + (size_t)tid * Hd;
        float a = 0.f;
#pragma unroll 8
        for (int k = 0; k < Hd; k++) a += hb[k] * w[k];
        lg[tid] = a;
    }
    __syncthreads();
    if (tid == 0) {
        float mx = -1e30f;
        for (int v = 0; v < Vc; v++) mx = fmaxf(mx, lg[v]);
        float sum = 0.f;
        for (int v = 0; v < Vc; v++) { float e = expf(lg[v] - mx); lg[v] = e; sum += e; }
        inv = 1.f / sum;
    }
    __syncthreads();
    if (tid < Vc) out[b * Vc + tid] = lg[tid] * inv;
}

extern "C" void kernel_launch(void* const* d_in, const int* in_sizes, int n_in,
                              void* d_out, int out_size) {
    const float* input = (const float*)d_in[0];
    const float* Qin   = (const float*)d_in[1];
    const int*   EOS   = (const int*)d_in[2];
    const int*   qlen  = (const int*)d_in[3];
    const int wo = (n_in >= 28) ? 6 : 4;
    const float* Wih_i = (const float*)d_in[wo + 0];
    const float* Whh_i = (const float*)d_in[wo + 1];
    const float* bih_i = (const float*)d_in[wo + 2];
    const float* bhh_i = (const float*)d_in[wo + 3];
    const float* Wih_q = (const float*)d_in[wo + 4];
    const float* Whh_q = (const float*)d_in[wo + 5];
    const float* bih_q = (const float*)d_in[wo + 6];
    const float* bhh_q = (const float*)d_in[wo + 7];
    const float* zW    = (const float*)d_in[wo + 8];
    const float* gW1   = (const float*)d_in[wo + 9];
    const float* gb1   = (const float*)d_in[wo + 10];
    const float* gW2   = (const float*)d_in[wo + 11];
    const float* gb2   = (const float*)d_in[wo + 12];
    const float* Wih_m = (const float*)d_in[wo + 13];
    const float* Whh_m = (const float*)d_in[wo + 14];
    const float* bih_m = (const float*)d_in[wo + 15];
    const float* bhh_m = (const float*)d_in[wo + 16];
    const float* Wa    = (const float*)d_in[wo + 17];
    const float* Wih_a = (const float*)d_in[wo + 18];
    const float* Whh_a = (const float*)d_in[wo + 19];
    const float* bih_a = (const float*)d_in[wo + 20];
    const float* bhh_a = (const float*)d_in[wo + 21];

    float* base = nullptr;
    cudaGetSymbolAddress((void**)&base, g_buf);
    float* GI_i   = base + O_GI_I;
    float* hist_i = base + O_HIST_I;
    float* GI_q   = base + O_GI_Q;
    float* hist_q = base + O_HIST_Q;
    float* Fd     = base + O_FD;
    float* P      = base + O_P;
    float* facts  = base + O_FACTS;
    float* hA     = base + O_HA;
    float* qv     = base + O_QV;
    float* Mt     = base + O_MT;
    float* uq     = base + O_UQ;
    float* Htc    = base + O_HTC;
    float* qm     = base + O_QM;
    float* cst    = base + O_CST;
    float* smv    = base + O_SM;
    float* sqv    = base + O_SQ;
    float* gib    = base + O_GIB;
    float* ghb    = base + O_GHB;
    float* xt     = base + O_XT;
    float* w7     = base + O_W7;
    float* w8     = base + O_W8;
    float* F0     = base + O_F0;
    float* P0     = base + O_P0;
    float* W0     = base + O_W0;
    float* Wd     = base + O_WD;

    cudaFuncSetAttribute(gru_cluster, cudaFuncAttributeMaxDynamicSharedMemorySize, SMEM_GRUC);
    cudaFuncSetAttribute(gemm_mma, cudaFuncAttributeMaxDynamicSharedMemorySize, SMEM_MMA);

    // ---- input GRU ----
    gemm_mma<<<dim3(H3 / 128, (Bc * Tc) / 128), 256, SMEM_MMA>>>(
        GI_i, input, Wih_i, bih_i, nullptr, Bc * Tc, H3, Gc, Gc, Gc, H3);
    gru_cluster<<<128, 256, SMEM_GRUC>>>(GI_i, hist_i, Whh_i, bhh_i, Tc);

    // ---- query GRU ----
    gemm_mma<<<dim3(H3 / 128, (Bc * Tqc) / 128), 256, SMEM_MMA>>>(
        GI_q, Qin, Wih_q, bih_q, nullptr, Bc * Tqc, H3, Gc, Gc, Gc, H3);
    gru_cluster<<<128, 256, SMEM_GRUC>>>(GI_q, hist_q, Whh_q, bhh_q, Tqc);

    // ---- gathers + depth-invariant precompute ----
    gathers<<<(Bc * Sc * Hd) / 256, 256>>>(facts, hist_i, EOS, qv, Mt, hist_q, qlen);
    pack_all<<<(GWc * 3 * Hd) / 256, 256>>>(W0, Wd, w7, w8, gW1);
    vecmat<<<Bc, Hd>>>(uq, qv, zW);
    build_F0<<<(Bc * Sc * Hd) / 256, 256>>>(F0, facts, qv);
    gemm_mma<<<dim3(GWc / 128, (Bc * Sc) / 128), 256, SMEM_MMA>>>(
        P0, F0, W0, nullptr, nullptr, Bc * Sc, GWc, 3 * Hd, 3 * Hd, 3 * Hd, GWc);

    // ---- episodic memory: m_depth = 3 ----
    for (int d = 0; d < 3; d++) {
        sdots_fq<<<Bc + (Bc * Sc * Hd) / 256, 256>>>(
            smv, sqv, facts, Mt, uq, zW, Fd, qm, qv);
        gemm_mma<<<dim3(GWc / 128, (Bc * Sc) / 128), 256, SMEM_MMA>>>(
            P, Fd, Wd, nullptr, P0, Bc * Sc, GWc, 2 * Hd, 2 * Hd, 2 * Hd, GWc);
        GP pc = {qm, gW1 + 256, gb1, cst, 512, 512, Zc, GWc, GWc};
        GP ph = {Mt,  Whh_m, bhh_m, ghb, Hd, Hd, Hd, H3, H3};
        gemm_nt2<<<dim3(H3 / 64, Bc / 64, 2), 256>>>(pc, ph);
        att_soft<<<Bc, 512>>>(Htc, P, cst, smv, sqv, w7, w8, gW2, gb2, facts);
        gemm_nt<<<dim3(H3 / 64, Bc / 64), 256>>>(
            gib, Htc, Wih_m, bih_m, Bc, H3, Hd, Hd, Hd, H3, 0);
        gru_gate<<<(Bc * Hd) / 256, 256>>>(Mt, gib, ghb, Mt);
    }

    // ---- answer module: a_len = 1 ----
    ysoft_xt<<<Bc, Hd>>>(xt, Mt, Wa, qv);
    {
        GP pg = {xt, Wih_a, bih_a, gib, Vc + Hd, Vc + Hd, Vc + Hd, H3, H3};
        GP ph = {Mt, Whh_a, bhh_a, ghb, Hd, Hd, Hd, H3, H3};
        gemm_nt2<<<dim3(H3 / 64, Bc / 64, 2), 256>>>(pg, ph);
    }
    gru_gate<<<(Bc * Hd) / 256, 256>>>(hA, gib, ghb, Mt);
    ysoft<<<Bc, Hd>>>((float*)d_out, hA, Wa);
}